// round 15
// baseline (speedup 1.0000x reference)
#include <cuda_runtime.h>
#include <cuda_bf16.h>
#include <cstdint>

// NOTE: identical to round-13/14 submission — final re-bench (#2) to settle
// whether the 4.4x anomaly + container failure were environmental. R13's ncu
// was provably corrupted (gemm=1.5us, HBM=3218% of spec). If this round also
// anomalies, next round reverts to the R12 two-barrier pipeline.

#define NN 40000
#define EE 1280000
#define FF 64
#define HH 128
#define RR 20
#define CC 32
#define GG 256
#define KT_MAX (RR * HH + HH)   // 2688

// ---------------- scratch (static device globals; zero-initialized at load) --
// INVARIANT: g_sums, g_cnt, g_pool, g_pcnt are all-zero at kernel_launch entry.
__device__ float g_sums[(size_t)NN * RR * HH];
__device__ float g_cnt[NN * RR];
__device__ float g_inv[NN * RR];
__device__ float g_h1[(size_t)NN * HH];
__device__ float g_h2[(size_t)NN * HH];
__device__ float g_pool[GG * HH];
__device__ float g_pcnt[GG];
__device__ __nv_bfloat16 g_wt_hi[(size_t)HH * KT_MAX];  // [HH, KT] K-major
__device__ __nv_bfloat16 g_wt_lo[(size_t)HH * KT_MAX];

__device__ __forceinline__ uint32_t pack_bf2(float a, float b) {
    __nv_bfloat162 t = __floats2bfloat162_rn(a, b);
    return *reinterpret_cast<uint32_t*>(&t);
}
__device__ __forceinline__ float bf_round(float a) {
    return __bfloat162float(__float2bfloat16_rn(a));
}

__device__ __forceinline__ void mma16816(float* c, uint32_t a0, uint32_t a1,
                                         uint32_t a2, uint32_t a3,
                                         uint32_t b0, uint32_t b1) {
    asm volatile(
        "mma.sync.aligned.m16n8k16.row.col.f32.bf16.bf16.f32 "
        "{%0,%1,%2,%3}, {%4,%5,%6,%7}, {%8,%9}, {%0,%1,%2,%3};"
        : "+f"(c[0]), "+f"(c[1]), "+f"(c[2]), "+f"(c[3])
        : "r"(a0), "r"(a1), "r"(a2), "r"(a3), "r"(b0), "r"(b1));
}
__device__ __forceinline__ void ldm_x4(uint32_t& r0, uint32_t& r1,
                                       uint32_t& r2, uint32_t& r3, uint32_t sa) {
    asm volatile("ldmatrix.sync.aligned.m8n8.x4.shared.b16 {%0,%1,%2,%3}, [%4];"
                 : "=r"(r0), "=r"(r1), "=r"(r2), "=r"(r3) : "r"(sa));
}
__device__ __forceinline__ void cp_async16(uint32_t sa, const void* g) {
    asm volatile("cp.async.cg.shared.global [%0], [%1], 16;" :: "r"(sa), "l"(g));
}
__device__ __forceinline__ void cp_commit() {
    asm volatile("cp.async.commit_group;" ::: "memory");
}
template <int N>
__device__ __forceinline__ void cp_wait() {
    asm volatile("cp.async.wait_group %0;" :: "n"(N) : "memory");
}

// ---------------- small kernels ----------------
__global__ void inv_kernel() {
    int i = blockIdx.x * blockDim.x + threadIdx.x;
    if (i < NN * RR) {
        float c = g_cnt[i];
        g_cnt[i] = 0.0f;
        g_inv[i] = 1.0f / fmaxf(c, 1.0f);
    }
}

__device__ __forceinline__ void red_add_v4(float* p, float4 v) {
    asm volatile("red.global.add.v4.f32 [%0], {%1, %2, %3, %4};"
                 :: "l"(p), "f"(v.x), "f"(v.y), "f"(v.z), "f"(v.w) : "memory");
}

template <int FIN, bool COUNT>
__global__ void scatter_kernel(const float* __restrict__ x,
                               const int* __restrict__ ei,
                               const int* __restrict__ et) {
    constexpr int CPE = FIN / 4;
    long long tid = (long long)blockIdx.x * blockDim.x + threadIdx.x;
    if (tid >= (long long)EE * CPE) return;
    int e = (int)(tid / CPE);
    int c = (int)(tid % CPE);
    int src = ei[e];
    int dst = ei[EE + e];
    int r = et[e];
    if (COUNT && c == 0) atomicAdd(&g_cnt[dst * RR + r], 1.0f);
    float4 v = reinterpret_cast<const float4*>(x + (size_t)src * FIN)[c];
    red_add_v4(&g_sums[(size_t)(dst * RR + r) * FIN + c * 4], v);
}

// Tiled transpose+split: W[k][n] (+root tail) -> g_wt_{hi,lo}[n][k], coalesced.
__global__ void conv_w_kernel(const float* __restrict__ W,
                              const float* __restrict__ root,
                              int K1, int KT) {
    __shared__ float tile[32][33];
    int kb = blockIdx.x * 32, nb = blockIdx.y * 32;
    int tx = threadIdx.x, ty = threadIdx.y;
#pragma unroll
    for (int i = 0; i < 4; i++) {
        int k = kb + ty + i * 8;
        float v = (k < K1) ? W[(size_t)k * HH + nb + tx]
                           : root[(size_t)(k - K1) * HH + nb + tx];
        tile[ty + i * 8][tx] = v;
    }
    __syncthreads();
#pragma unroll
    for (int i = 0; i < 4; i++) {
        int n = nb + ty + i * 8;
        int k = kb + tx;
        float v = tile[tx][ty + i * 8];
        float h = bf_round(v);
        g_wt_hi[(size_t)n * KT + k] = __float2bfloat16_rn(v);
        g_wt_lo[(size_t)n * KT + k] = __float2bfloat16_rn(v - h);
    }
}

// ---------------- mma.sync GEMM (64x128 tile, occ 3, reg-carry A) ----------
template <int FIN>
__global__ __launch_bounds__(256, 3) void gemm_mma(
    const float* __restrict__ xin, const float* __restrict__ bias,
    float* __restrict__ out) {
    constexpr int K1 = RR * FIN;
    constexpr int KT = K1 + FIN;
    constexpr int BK = 32;
    constexpr int NC = KT / BK;
    constexpr int SHIFT = (FIN == 64) ? 6 : 7;
    constexpr int LDS_K = BK + 8;               // bf16 units (80B row)
    constexpr int A_MAT = 64 * LDS_K;           // 2560 elems
    constexpr int B_MAT = 128 * LDS_K;          // 5120 elems
    constexpr int B_HI = 2 * A_MAT, B_LO = 2 * A_MAT + B_MAT;
    constexpr int STAGE_E = 2 * A_MAT + 2 * B_MAT;   // 15360 elems
    constexpr uint32_t STAGE_B = STAGE_E * 2;        // 30720 bytes

    extern __shared__ __align__(16) __nv_bfloat16 smem[];

    const int t = threadIdx.x;
    const int wid = t >> 5;
    const int lane = t & 31;
    const int wm = wid & 1;        // warp m index 0..1
    const int wn = wid >> 1;       // warp n index 0..3
    const int m0 = blockIdx.x * 64;

    const int arowL = t >> 2;      // 0..63
    const int aq = t & 3;          // quarter: cols aq*8 .. aq*8+7
    const int rowL = m0 + arowL;   // always < NN (grid*64 == NN)

    const uint32_t sbase = (uint32_t)__cvta_generic_to_shared(smem);

    float acc[2][4][4];
#pragma unroll
    for (int i = 0; i < 2; i++)
#pragma unroll
        for (int j = 0; j < 4; j++)
#pragma unroll
            for (int q = 0; q < 4; q++) acc[i][j][q] = 0.f;

    float rA[8];

    auto issue_B = [&](int c, int buf) {
        const int k0 = c * BK;
        const int row = t >> 1;
        const int seg = (t & 1) * 2;
        const __nv_bfloat16* gh = g_wt_hi + (size_t)row * KT + k0 + seg * 8;
        const __nv_bfloat16* gl = g_wt_lo + (size_t)row * KT + k0 + seg * 8;
        uint32_t sh = sbase + buf * STAGE_B + (uint32_t)(B_HI + row * LDS_K + seg * 8) * 2;
        uint32_t sl = sbase + buf * STAGE_B + (uint32_t)(B_LO + row * LDS_K + seg * 8) * 2;
        cp_async16(sh, gh);       cp_async16(sh + 16, gh + 8);
        cp_async16(sl, gl);       cp_async16(sl + 16, gl + 8);
    };

    auto ldg_A = [&](int c) {
        const int k0 = c * BK;
        if (k0 < K1) {
            float* gp = &g_sums[(size_t)rowL * K1 + k0 + aq * 8];
            float s = g_inv[rowL * RR + (k0 >> SHIFT)];
            float4 v0 = reinterpret_cast<const float4*>(gp)[0];
            float4 v1 = reinterpret_cast<const float4*>(gp)[1];
            rA[0] = v0.x * s; rA[1] = v0.y * s; rA[2] = v0.z * s; rA[3] = v0.w * s;
            rA[4] = v1.x * s; rA[5] = v1.y * s; rA[6] = v1.z * s; rA[7] = v1.w * s;
            float4 z = make_float4(0.f, 0.f, 0.f, 0.f);
            reinterpret_cast<float4*>(gp)[0] = z;   // safe: same-thread ordering
            reinterpret_cast<float4*>(gp)[1] = z;
        } else {
            const float* src = xin + (size_t)rowL * FIN + (k0 - K1) + aq * 8;
            float4 v0 = reinterpret_cast<const float4*>(src)[0];
            float4 v1 = reinterpret_cast<const float4*>(src)[1];
            rA[0] = v0.x; rA[1] = v0.y; rA[2] = v0.z; rA[3] = v0.w;
            rA[4] = v1.x; rA[5] = v1.y; rA[6] = v1.z; rA[7] = v1.w;
        }
    };

    auto sts_A = [&](int buf) {
        uint32_t h[4], l[4];
#pragma unroll
        for (int j = 0; j < 4; j++) {
            float a = rA[2 * j], b = rA[2 * j + 1];
            h[j] = pack_bf2(a, b);
            l[j] = pack_bf2(a - bf_round(a), b - bf_round(b));
        }
        __nv_bfloat16* base = smem + buf * STAGE_E + arowL * LDS_K + aq * 8;
        *reinterpret_cast<uint4*>(base)         = make_uint4(h[0], h[1], h[2], h[3]);
        *reinterpret_cast<uint4*>(base + A_MAT) = make_uint4(l[0], l[1], l[2], l[3]);
    };

    const int lmat = lane >> 3;
    const int lr = lane & 7;

    auto compute = [&](int buf) {
        const uint32_t s = sbase + buf * STAGE_B;
#pragma unroll
        for (int ks = 0; ks < 2; ks++) {
            const int kb = ks * 16;
            uint32_t ah[2][4], al[2][4];
#pragma unroll
            for (int mi = 0; mi < 2; mi++) {
                int arow = wm * 32 + mi * 16 + (lmat & 1) * 8 + lr;
                int ak = kb + (lmat >> 1) * 8;
                uint32_t aA = s + (uint32_t)(arow * LDS_K + ak) * 2;
                ldm_x4(ah[mi][0], ah[mi][1], ah[mi][2], ah[mi][3], aA);
                ldm_x4(al[mi][0], al[mi][1], al[mi][2], al[mi][3], aA + A_MAT * 2);
            }
#pragma unroll
            for (int g = 0; g < 2; g++) {
                int brow = wn * 32 + (2 * g + (lmat >> 1)) * 8 + lr;
                int bk = kb + (lmat & 1) * 8;
                uint32_t bB = s + (uint32_t)(B_HI + brow * LDS_K + bk) * 2;
                uint32_t bh[4], bl[4];
                ldm_x4(bh[0], bh[1], bh[2], bh[3], bB);
                ldm_x4(bl[0], bl[1], bl[2], bl[3], bB + B_MAT * 2);
#pragma unroll
                for (int sub = 0; sub < 2; sub++) {
                    int ni = 2 * g + sub;
                    uint32_t b0h = bh[2 * sub], b1h = bh[2 * sub + 1];
                    uint32_t b0l = bl[2 * sub], b1l = bl[2 * sub + 1];
#pragma unroll
                    for (int mi = 0; mi < 2; mi++) {
                        mma16816(acc[mi][ni], ah[mi][0], ah[mi][1], ah[mi][2], ah[mi][3], b0h, b1h);
                        mma16816(acc[mi][ni], al[mi][0], al[mi][1], al[mi][2], al[mi][3], b0h, b1h);
                        mma16816(acc[mi][ni], ah[mi][0], ah[mi][1], ah[mi][2], ah[mi][3], b0l, b1l);
                    }
                }
            }
        }
    };

    // prologue: stage 0 fully resident
    issue_B(0, 0);
    cp_commit();
    ldg_A(0);
    sts_A(0);
    cp_wait<0>();
    __syncthreads();

    for (int c = 0; c < NC; c++) {
        const int buf = c & 1;
        const bool more = (c + 1 < NC);
        if (more) {
            issue_B(c + 1, buf ^ 1);   // buf^1 free: all warps passed prev barrier
            cp_commit();
            ldg_A(c + 1);              // LDG latency hidden under compute
        }
        compute(buf);
        if (more) {
            sts_A(buf ^ 1);            // rA ready by now (post-compute)
            cp_wait<0>();
        }
        __syncthreads();               // single barrier per chunk
    }

    // epilogue: bias + relu
    const int qrow = lane >> 2;
    const int qc = (lane & 3) * 2;
#pragma unroll
    for (int mi = 0; mi < 2; mi++) {
#pragma unroll
        for (int ni = 0; ni < 4; ni++) {
            int col = wn * 32 + ni * 8 + qc;
            float b0 = bias[col], b1 = bias[col + 1];
            int r0 = m0 + wm * 32 + mi * 16 + qrow;
            float2 v;
            v.x = fmaxf(acc[mi][ni][0] + b0, 0.f);
            v.y = fmaxf(acc[mi][ni][1] + b1, 0.f);
            *reinterpret_cast<float2*>(&out[(size_t)r0 * HH + col]) = v;
            int r1 = r0 + 8;
            v.x = fmaxf(acc[mi][ni][2] + b0, 0.f);
            v.y = fmaxf(acc[mi][ni][3] + b1, 0.f);
            *reinterpret_cast<float2*>(&out[(size_t)r1 * HH + col]) = v;
        }
    }
}

// ---------------- pool + fc ----------------
__global__ void pcnt_kernel(const int* __restrict__ batch) {
    int n = blockIdx.x * blockDim.x + threadIdx.x;
    if (n < NN) atomicAdd(&g_pcnt[batch[n]], 1.0f);
}

__global__ void pool_kernel(const int* __restrict__ batch) {
    int tid = blockIdx.x * blockDim.x + threadIdx.x;
    if (tid >= NN * (HH / 4)) return;
    int n = tid / (HH / 4);
    int c = tid % (HH / 4);
    int g = batch[n];
    float4 v = reinterpret_cast<const float4*>(g_h2)[tid];
    red_add_v4(&g_pool[g * HH + c * 4], v);
}

__global__ void final_kernel(const float* __restrict__ fc_w,
                             const float* __restrict__ fc_b,
                             float* __restrict__ out) {
    int g = blockIdx.x;
    int c = threadIdx.x;
    float inv = 1.0f / fmaxf(g_pcnt[g], 1.0f);
    float acc = 0.f;
#pragma unroll 8
    for (int h = 0; h < HH; h++) acc += g_pool[g * HH + h] * fc_w[h * CC + c];
    out[g * CC + c] = acc * inv + fc_b[c];
    __syncthreads();
    reinterpret_cast<float4*>(&g_pool[g * HH])[c] = make_float4(0.f, 0.f, 0.f, 0.f);
    if (c == 0) g_pcnt[g] = 0.f;
}

// ---------------- launch ----------------
extern "C" void kernel_launch(void* const* d_in, const int* in_sizes, int n_in,
                              void* d_out, int out_size) {
    const float* x     = (const float*)d_in[0];
    const int* ei      = (const int*)d_in[1];
    const int* et      = (const int*)d_in[2];
    const int* bat     = (const int*)d_in[3];
    const float* W1    = (const float*)d_in[4];
    const float* root1 = (const float*)d_in[5];
    const float* b1    = (const float*)d_in[6];
    const float* W2    = (const float*)d_in[7];
    const float* root2 = (const float*)d_in[8];
    const float* b2    = (const float*)d_in[9];
    const float* fcw   = (const float*)d_in[10];
    const float* fcb   = (const float*)d_in[11];
    float* out         = (float*)d_out;

    void *p_h1, *p_h2;
    cudaGetSymbolAddress(&p_h1, g_h1);
    cudaGetSymbolAddress(&p_h2, g_h2);
    float* h1 = (float*)p_h1;
    float* h2 = (float*)p_h2;

    // dyn smem: 2 stages x 30720 B = 61440 B  (3 CTAs/SM -> 184 KB)
    const int DYN = 2 * 30720;
    cudaFuncSetAttribute(gemm_mma<FF>, cudaFuncAttributeMaxDynamicSharedMemorySize, DYN);
    cudaFuncSetAttribute(gemm_mma<HH>, cudaFuncAttributeMaxDynamicSharedMemorySize, DYN);

    const int GEMM_GRID = NN / 64;   // 625, exact

    // Layer 1 (scatter also accumulates per-(dst,rel) edge counts)
    {
        dim3 grid((RR * FF + FF) / 32, HH / 32), blk(32, 8);
        conv_w_kernel<<<grid, blk>>>(W1, root1, RR * FF, RR * FF + FF);
    }
    scatter_kernel<FF, true><<<(EE * (FF / 4) + 255) / 256, 256>>>(x, ei, et);
    inv_kernel<<<(NN * RR + 255) / 256, 256>>>();   // also re-zeroes g_cnt
    gemm_mma<FF><<<GEMM_GRID, 256, DYN>>>(x, b1, h1);

    // Layer 2
    {
        dim3 grid((RR * HH + HH) / 32, HH / 32), blk(32, 8);
        conv_w_kernel<<<grid, blk>>>(W2, root2, RR * HH, RR * HH + HH);
    }
    scatter_kernel<HH, false><<<(EE * (HH / 4) + 255) / 256, 256>>>(h1, ei, et);
    gemm_mma<HH><<<GEMM_GRID, 256, DYN>>>(h1, b2, h2);

    // Global mean pool + FC (final re-zeroes g_pool / g_pcnt)
    pcnt_kernel<<<(NN + 255) / 256, 256>>>(bat);
    pool_kernel<<<(NN * (HH / 4) + 255) / 256, 256>>>(bat);
    final_kernel<<<GG, CC>>>(fcw, fcb, out);
}

// round 16
// speedup vs baseline: 4.9522x; 4.9522x over previous
#include <cuda_runtime.h>
#include <cuda_bf16.h>
#include <cstdint>

// Base: round-12 structure (measured 1118us) — the R13 reg-carry variant
// reproducibly ran ~5ms (twice) and is abandoned. Additions vs R12:
//   1. prefetch.global.L2 of next A chunk inside load_A
//   2. pcnt fused into pool_kernel

#define NN 40000
#define EE 1280000
#define FF 64
#define HH 128
#define RR 20
#define CC 32
#define GG 256
#define KT_MAX (RR * HH + HH)   // 2688

// ---------------- scratch (static device globals; zero-initialized at load) --
// INVARIANT: g_sums, g_cnt, g_pool, g_pcnt are all-zero at kernel_launch entry.
__device__ float g_sums[(size_t)NN * RR * HH];
__device__ float g_cnt[NN * RR];
__device__ float g_inv[NN * RR];
__device__ float g_h1[(size_t)NN * HH];
__device__ float g_h2[(size_t)NN * HH];
__device__ float g_pool[GG * HH];
__device__ float g_pcnt[GG];
__device__ __nv_bfloat16 g_wt_hi[(size_t)HH * KT_MAX];  // [HH, KT] K-major
__device__ __nv_bfloat16 g_wt_lo[(size_t)HH * KT_MAX];

__device__ __forceinline__ uint32_t pack_bf2(float a, float b) {
    __nv_bfloat162 t = __floats2bfloat162_rn(a, b);
    return *reinterpret_cast<uint32_t*>(&t);
}
__device__ __forceinline__ float bf_round(float a) {
    return __bfloat162float(__float2bfloat16_rn(a));
}

__device__ __forceinline__ void mma16816(float* c, uint32_t a0, uint32_t a1,
                                         uint32_t a2, uint32_t a3,
                                         uint32_t b0, uint32_t b1) {
    asm volatile(
        "mma.sync.aligned.m16n8k16.row.col.f32.bf16.bf16.f32 "
        "{%0,%1,%2,%3}, {%4,%5,%6,%7}, {%8,%9}, {%0,%1,%2,%3};"
        : "+f"(c[0]), "+f"(c[1]), "+f"(c[2]), "+f"(c[3])
        : "r"(a0), "r"(a1), "r"(a2), "r"(a3), "r"(b0), "r"(b1));
}
__device__ __forceinline__ void ldm_x4(uint32_t& r0, uint32_t& r1,
                                       uint32_t& r2, uint32_t& r3, uint32_t sa) {
    asm volatile("ldmatrix.sync.aligned.m8n8.x4.shared.b16 {%0,%1,%2,%3}, [%4];"
                 : "=r"(r0), "=r"(r1), "=r"(r2), "=r"(r3) : "r"(sa));
}
__device__ __forceinline__ void cp_async16(uint32_t sa, const void* g) {
    asm volatile("cp.async.cg.shared.global [%0], [%1], 16;" :: "r"(sa), "l"(g));
}
__device__ __forceinline__ void cp_commit() {
    asm volatile("cp.async.commit_group;" ::: "memory");
}
template <int N>
__device__ __forceinline__ void cp_wait() {
    asm volatile("cp.async.wait_group %0;" :: "n"(N) : "memory");
}
__device__ __forceinline__ void prefetch_l2(const void* p) {
    asm volatile("prefetch.global.L2 [%0];" :: "l"(p));
}

// ---------------- small kernels ----------------
__global__ void inv_kernel() {
    int i = blockIdx.x * blockDim.x + threadIdx.x;
    if (i < NN * RR) {
        float c = g_cnt[i];
        g_cnt[i] = 0.0f;
        g_inv[i] = 1.0f / fmaxf(c, 1.0f);
    }
}

__device__ __forceinline__ void red_add_v4(float* p, float4 v) {
    asm volatile("red.global.add.v4.f32 [%0], {%1, %2, %3, %4};"
                 :: "l"(p), "f"(v.x), "f"(v.y), "f"(v.z), "f"(v.w) : "memory");
}
__device__ __forceinline__ void red_add_f32(float* p, float v) {
    asm volatile("red.global.add.f32 [%0], %1;" :: "l"(p), "f"(v) : "memory");
}

template <int FIN, bool COUNT>
__global__ void scatter_kernel(const float* __restrict__ x,
                               const int* __restrict__ ei,
                               const int* __restrict__ et) {
    constexpr int CPE = FIN / 4;
    long long tid = (long long)blockIdx.x * blockDim.x + threadIdx.x;
    if (tid >= (long long)EE * CPE) return;
    int e = (int)(tid / CPE);
    int c = (int)(tid % CPE);
    int src = ei[e];
    int dst = ei[EE + e];
    int r = et[e];
    if (COUNT && c == 0) atomicAdd(&g_cnt[dst * RR + r], 1.0f);
    float4 v = reinterpret_cast<const float4*>(x + (size_t)src * FIN)[c];
    red_add_v4(&g_sums[(size_t)(dst * RR + r) * FIN + c * 4], v);
}

// Tiled transpose+split: W[k][n] (+root tail) -> g_wt_{hi,lo}[n][k], coalesced.
__global__ void conv_w_kernel(const float* __restrict__ W,
                              const float* __restrict__ root,
                              int K1, int KT) {
    __shared__ float tile[32][33];
    int kb = blockIdx.x * 32, nb = blockIdx.y * 32;
    int tx = threadIdx.x, ty = threadIdx.y;
#pragma unroll
    for (int i = 0; i < 4; i++) {
        int k = kb + ty + i * 8;
        float v = (k < K1) ? W[(size_t)k * HH + nb + tx]
                           : root[(size_t)(k - K1) * HH + nb + tx];
        tile[ty + i * 8][tx] = v;
    }
    __syncthreads();
#pragma unroll
    for (int i = 0; i < 4; i++) {
        int n = nb + ty + i * 8;
        int k = kb + tx;
        float v = tile[tx][ty + i * 8];
        float h = bf_round(v);
        g_wt_hi[(size_t)n * KT + k] = __float2bfloat16_rn(v);
        g_wt_lo[(size_t)n * KT + k] = __float2bfloat16_rn(v - h);
    }
}

// ---------------- mma.sync GEMM (64x128 tile, occ 3) — R12 structure ------
// out[N,HH] = relu( Ahat[N,K1]@W + xin@root + bias ), fused K = K1 + FIN.
// bf16 hi/lo: D = Ah@Bh + Al@Bh + Ah@Bl.
// CTA tile 64x128, BK=32, 8 warps (2m x 4n), warp tile 32x32 (acc=32 regs).
// B double-buffered via cp.async; A is LDG->convert->STS at chunk start,
// with an L2 prefetch of the NEXT chunk's A to shorten the exposed LDG.
// Re-zeroes each g_sums chunk after reading (read-once per element).
template <int FIN>
__global__ __launch_bounds__(256, 3) void gemm_mma(
    const float* __restrict__ xin, const float* __restrict__ bias,
    float* __restrict__ out) {
    constexpr int K1 = RR * FIN;
    constexpr int KT = K1 + FIN;
    constexpr int BK = 32;
    constexpr int NC = KT / BK;
    constexpr int SHIFT = (FIN == 64) ? 6 : 7;
    constexpr int LDS_K = BK + 8;               // bf16 units (80B row)
    constexpr int A_MAT = 64 * LDS_K;           // 2560 elems
    constexpr int B_MAT = 128 * LDS_K;          // 5120 elems
    constexpr int B_HI = 2 * A_MAT, B_LO = 2 * A_MAT + B_MAT;
    constexpr int STAGE_E = 2 * A_MAT + 2 * B_MAT;   // 15360 elems
    constexpr uint32_t STAGE_B = STAGE_E * 2;        // 30720 bytes

    extern __shared__ __align__(16) __nv_bfloat16 smem[];

    const int t = threadIdx.x;
    const int wid = t >> 5;
    const int lane = t & 31;
    const int wm = wid & 1;        // warp m index 0..1
    const int wn = wid >> 1;       // warp n index 0..3
    const int m0 = blockIdx.x * 64;

    // A load mapping: 64 rows x 32 cols fp32 over 256 threads -> 8 floats each
    const int arowL = t >> 2;      // 0..63
    const int aq = t & 3;          // quarter: cols aq*8 .. aq*8+7
    const int rowL = m0 + arowL;   // always < NN (grid*64 == NN)

    const uint32_t sbase = (uint32_t)__cvta_generic_to_shared(smem);

    float acc[2][4][4];
#pragma unroll
    for (int i = 0; i < 2; i++)
#pragma unroll
        for (int j = 0; j < 4; j++)
#pragma unroll
            for (int q = 0; q < 4; q++) acc[i][j][q] = 0.f;

    // B cp.async mapping: 128 rows x 32 bf16 -> 2 threads/row x 2x16B each
    auto issue_B = [&](int c, int buf) {
        const int k0 = c * BK;
        const int row = t >> 1;
        const int seg = (t & 1) * 2;
        const __nv_bfloat16* gh = g_wt_hi + (size_t)row * KT + k0 + seg * 8;
        const __nv_bfloat16* gl = g_wt_lo + (size_t)row * KT + k0 + seg * 8;
        uint32_t sh = sbase + buf * STAGE_B + (uint32_t)(B_HI + row * LDS_K + seg * 8) * 2;
        uint32_t sl = sbase + buf * STAGE_B + (uint32_t)(B_LO + row * LDS_K + seg * 8) * 2;
        cp_async16(sh, gh);       cp_async16(sh + 16, gh + 8);
        cp_async16(sl, gl);       cp_async16(sl + 16, gl + 8);
    };

    // A: LDG fp32 -> scale -> bf16 hi/lo -> STS; zero the chunk; L2-prefetch
    // the next chunk's A region (no destination register, no live range).
    auto load_A = [&](int c, int buf) {
        const int k0 = c * BK;
        const float* src;
        float s;
        float* zp = nullptr;
        if (k0 < K1) {
            float* gp = &g_sums[(size_t)rowL * K1 + k0 + aq * 8];
            src = gp;
            s = g_inv[rowL * RR + (k0 >> SHIFT)];
            zp = gp;
        } else {
            src = xin + (size_t)rowL * FIN + (k0 - K1) + aq * 8;
            s = 1.0f;
        }
        // prefetch next chunk's A (same row, +BK columns) into L2
        const int k0n = k0 + BK;
        if (k0n < K1) {
            prefetch_l2(&g_sums[(size_t)rowL * K1 + k0n + aq * 8]);
        } else if (k0n < KT) {
            prefetch_l2(xin + (size_t)rowL * FIN + (k0n - K1) + aq * 8);
        }
        float4 v0 = reinterpret_cast<const float4*>(src)[0];
        float4 v1 = reinterpret_cast<const float4*>(src)[1];
        float f[8] = {v0.x * s, v0.y * s, v0.z * s, v0.w * s,
                      v1.x * s, v1.y * s, v1.z * s, v1.w * s};
        uint32_t h[4], l[4];
#pragma unroll
        for (int j = 0; j < 4; j++) {
            float a = f[2 * j], b = f[2 * j + 1];
            h[j] = pack_bf2(a, b);
            l[j] = pack_bf2(a - bf_round(a), b - bf_round(b));
        }
        __nv_bfloat16* base = smem + buf * STAGE_E + arowL * LDS_K + aq * 8;
        *reinterpret_cast<uint4*>(base)         = make_uint4(h[0], h[1], h[2], h[3]);
        *reinterpret_cast<uint4*>(base + A_MAT) = make_uint4(l[0], l[1], l[2], l[3]);
        if (zp) {
            float4 z = make_float4(0.f, 0.f, 0.f, 0.f);
            reinterpret_cast<float4*>(zp)[0] = z;
            reinterpret_cast<float4*>(zp)[1] = z;
        }
    };

    const int lmat = lane >> 3;   // which 8x8 within ldmatrix.x4
    const int lr = lane & 7;

    auto compute = [&](int buf) {
        const uint32_t s = sbase + buf * STAGE_B;
#pragma unroll
        for (int ks = 0; ks < 2; ks++) {
            const int kb = ks * 16;
            uint32_t ah[2][4], al[2][4];
#pragma unroll
            for (int mi = 0; mi < 2; mi++) {
                int arow = wm * 32 + mi * 16 + (lmat & 1) * 8 + lr;
                int ak = kb + (lmat >> 1) * 8;
                uint32_t aA = s + (uint32_t)(arow * LDS_K + ak) * 2;
                ldm_x4(ah[mi][0], ah[mi][1], ah[mi][2], ah[mi][3], aA);
                ldm_x4(al[mi][0], al[mi][1], al[mi][2], al[mi][3], aA + A_MAT * 2);
            }
#pragma unroll
            for (int g = 0; g < 2; g++) {
                int brow = wn * 32 + (2 * g + (lmat >> 1)) * 8 + lr;
                int bk = kb + (lmat & 1) * 8;
                uint32_t bB = s + (uint32_t)(B_HI + brow * LDS_K + bk) * 2;
                uint32_t bh[4], bl[4];
                ldm_x4(bh[0], bh[1], bh[2], bh[3], bB);
                ldm_x4(bl[0], bl[1], bl[2], bl[3], bB + B_MAT * 2);
#pragma unroll
                for (int sub = 0; sub < 2; sub++) {
                    int ni = 2 * g + sub;
                    uint32_t b0h = bh[2 * sub], b1h = bh[2 * sub + 1];
                    uint32_t b0l = bl[2 * sub], b1l = bl[2 * sub + 1];
#pragma unroll
                    for (int mi = 0; mi < 2; mi++) {
                        mma16816(acc[mi][ni], ah[mi][0], ah[mi][1], ah[mi][2], ah[mi][3], b0h, b1h);
                        mma16816(acc[mi][ni], al[mi][0], al[mi][1], al[mi][2], al[mi][3], b0h, b1h);
                        mma16816(acc[mi][ni], ah[mi][0], ah[mi][1], ah[mi][2], ah[mi][3], b0l, b1l);
                    }
                }
            }
        }
    };

    // prologue: prefetch B(0)
    issue_B(0, 0);
    cp_commit();

    for (int c = 0; c < NC; c++) {
        const int buf = c & 1;
        if (c + 1 < NC) {
            issue_B(c + 1, buf ^ 1);   // safe: buf^1 fully consumed (post-sync2 of c-1)
            cp_commit();
            load_A(c, buf);
            cp_wait<1>();              // B(c) arrived; B(c+1) may stay in flight
        } else {
            load_A(c, buf);
            cp_wait<0>();
        }
        __syncthreads();               // A(c)+B(c) visible to all
        compute(buf);
        __syncthreads();               // close compute before next overwrite
    }

    // epilogue: bias + relu
    const int qrow = lane >> 2;
    const int qc = (lane & 3) * 2;
#pragma unroll
    for (int mi = 0; mi < 2; mi++) {
#pragma unroll
        for (int ni = 0; ni < 4; ni++) {
            int col = wn * 32 + ni * 8 + qc;
            float b0 = bias[col], b1 = bias[col + 1];
            int r0 = m0 + wm * 32 + mi * 16 + qrow;
            float2 v;
            v.x = fmaxf(acc[mi][ni][0] + b0, 0.f);
            v.y = fmaxf(acc[mi][ni][1] + b1, 0.f);
            *reinterpret_cast<float2*>(&out[(size_t)r0 * HH + col]) = v;
            int r1 = r0 + 8;
            v.x = fmaxf(acc[mi][ni][2] + b0, 0.f);
            v.y = fmaxf(acc[mi][ni][3] + b1, 0.f);
            *reinterpret_cast<float2*>(&out[(size_t)r1 * HH + col]) = v;
        }
    }
}

// ---------------- pool + fc ----------------
// pool also accumulates per-graph node counts (fused pcnt: c==0 lane).
__global__ void pool_kernel(const int* __restrict__ batch) {
    int tid = blockIdx.x * blockDim.x + threadIdx.x;
    if (tid >= NN * (HH / 4)) return;
    int n = tid / (HH / 4);
    int c = tid % (HH / 4);
    int g = batch[n];
    if (c == 0) red_add_f32(&g_pcnt[g], 1.0f);
    float4 v = reinterpret_cast<const float4*>(g_h2)[tid];
    red_add_v4(&g_pool[g * HH + c * 4], v);
}

// FC over pooled means; re-zeroes g_pool row + g_pcnt entry afterwards.
__global__ void final_kernel(const float* __restrict__ fc_w,
                             const float* __restrict__ fc_b,
                             float* __restrict__ out) {
    int g = blockIdx.x;
    int c = threadIdx.x;
    float inv = 1.0f / fmaxf(g_pcnt[g], 1.0f);
    float acc = 0.f;
#pragma unroll 8
    for (int h = 0; h < HH; h++) acc += g_pool[g * HH + h] * fc_w[h * CC + c];
    out[g * CC + c] = acc * inv + fc_b[c];
    __syncthreads();
    reinterpret_cast<float4*>(&g_pool[g * HH])[c] = make_float4(0.f, 0.f, 0.f, 0.f);
    if (c == 0) g_pcnt[g] = 0.f;
}

// ---------------- launch ----------------
extern "C" void kernel_launch(void* const* d_in, const int* in_sizes, int n_in,
                              void* d_out, int out_size) {
    const float* x     = (const float*)d_in[0];
    const int* ei      = (const int*)d_in[1];
    const int* et      = (const int*)d_in[2];
    const int* bat     = (const int*)d_in[3];
    const float* W1    = (const float*)d_in[4];
    const float* root1 = (const float*)d_in[5];
    const float* b1    = (const float*)d_in[6];
    const float* W2    = (const float*)d_in[7];
    const float* root2 = (const float*)d_in[8];
    const float* b2    = (const float*)d_in[9];
    const float* fcw   = (const float*)d_in[10];
    const float* fcb   = (const float*)d_in[11];
    float* out         = (float*)d_out;

    void *p_h1, *p_h2;
    cudaGetSymbolAddress(&p_h1, g_h1);
    cudaGetSymbolAddress(&p_h2, g_h2);
    float* h1 = (float*)p_h1;
    float* h2 = (float*)p_h2;

    // dyn smem: 2 stages x 30720 B = 61440 B  (3 CTAs/SM -> 184 KB)
    const int DYN = 2 * 30720;
    cudaFuncSetAttribute(gemm_mma<FF>, cudaFuncAttributeMaxDynamicSharedMemorySize, DYN);
    cudaFuncSetAttribute(gemm_mma<HH>, cudaFuncAttributeMaxDynamicSharedMemorySize, DYN);

    const int GEMM_GRID = NN / 64;   // 625, exact

    // Layer 1 (scatter also accumulates per-(dst,rel) edge counts)
    {
        dim3 grid((RR * FF + FF) / 32, HH / 32), blk(32, 8);
        conv_w_kernel<<<grid, blk>>>(W1, root1, RR * FF, RR * FF + FF);
    }
    scatter_kernel<FF, true><<<(EE * (FF / 4) + 255) / 256, 256>>>(x, ei, et);
    inv_kernel<<<(NN * RR + 255) / 256, 256>>>();   // also re-zeroes g_cnt
    gemm_mma<FF><<<GEMM_GRID, 256, DYN>>>(x, b1, h1);

    // Layer 2
    {
        dim3 grid((RR * HH + HH) / 32, HH / 32), blk(32, 8);
        conv_w_kernel<<<grid, blk>>>(W2, root2, RR * HH, RR * HH + HH);
    }
    scatter_kernel<HH, false><<<(EE * (HH / 4) + 255) / 256, 256>>>(h1, ei, et);
    gemm_mma<HH><<<GEMM_GRID, 256, DYN>>>(h1, b2, h2);

    // Global mean pool (fused pcnt) + FC (final re-zeroes g_pool / g_pcnt)
    pool_kernel<<<(NN * (HH / 4) + 255) / 256, 256>>>(bat);
    final_kernel<<<GG, CC>>>(fcw, fcb, out);
}